// round 16
// baseline (speedup 1.0000x reference)
#include <cuda_runtime.h>
#include <cuda_fp16.h>
#include <cstdint>

// ---------------------------------------------------------------------------
// Problem constants
// ---------------------------------------------------------------------------
#define BS_ROWS 4096      // B*S
#define NHEAD   8
#define DIM     64        // d == D_head
#define NLAND   2048      // landmarks per head
#define DOUT    512
#define EPS_C   1e-12f
#define C2EXP   (-0.72134752044448f)    // -0.5 * log2(e)
#define LOG2E   (1.44269504088896f)
#define BM      256       // rows per CTA (32 per warp)
#define NCTAS   128       // fused grid size (16 x 8) -- all resident (<=148 SMs)

// ---------------------------------------------------------------------------
// Device-global scratch
// ---------------------------------------------------------------------------
__device__ float  g_cR2[NHEAD * NLAND];                 // C2EXP * ||R_n||^2
__device__ __half g_RH[NHEAD * NLAND * DIM];            // R fp16 [h][n][d] (single)
__device__ __half g_WPH[NHEAD * 72 * NLAND];            // W' fp16 [h][72][n] (single)
                                                        // rows 0-63: qa*W^T; 64: 1; 65: qa; 66-71: 0
__device__ __half g_Y [BS_ROWS * DOUT];                 // y fp16 [row][col]
__device__ __half g_WOH[DOUT * DOUT];                   // W_O^T fp16 [col][k] (single)
__device__ int    g_barr[16];                           // per-row-group barrier

// ---------------------------------------------------------------------------
// PTX helpers
// ---------------------------------------------------------------------------
__device__ __forceinline__ uint32_t smem_u32(const void* p) {
    return (uint32_t)__cvta_generic_to_shared(p);
}
__device__ __forceinline__ void cp16(uint32_t s, const void* g) {
    asm volatile("cp.async.cg.shared.global [%0], [%1], 16;" :: "r"(s), "l"(g));
}
#define CP_COMMIT() asm volatile("cp.async.commit_group;" ::: "memory")
#define CP_WAIT1()  asm volatile("cp.async.wait_group 1;" ::: "memory")
#define CP_WAIT0()  asm volatile("cp.async.wait_group 0;" ::: "memory")

__device__ __forceinline__ void ldm_x4(uint32_t* f, uint32_t addr) {
    asm volatile("ldmatrix.sync.aligned.m8n8.x4.shared.b16 {%0,%1,%2,%3}, [%4];"
        : "=r"(f[0]), "=r"(f[1]), "=r"(f[2]), "=r"(f[3]) : "r"(addr));
}
__device__ __forceinline__ void ldm_x2(uint32_t* f, uint32_t addr) {
    asm volatile("ldmatrix.sync.aligned.m8n8.x2.shared.b16 {%0,%1}, [%2];"
        : "=r"(f[0]), "=r"(f[1]) : "r"(addr));
}
__device__ __forceinline__ void mma_f16(float* c, const uint32_t* a,
                                        uint32_t b0, uint32_t b1) {
    asm volatile(
        "mma.sync.aligned.m16n8k16.row.col.f32.f16.f16.f32 "
        "{%0,%1,%2,%3}, {%4,%5,%6,%7}, {%8,%9}, {%0,%1,%2,%3};"
        : "+f"(c[0]), "+f"(c[1]), "+f"(c[2]), "+f"(c[3])
        : "r"(a[0]), "r"(a[1]), "r"(a[2]), "r"(a[3]), "r"(b0), "r"(b1));
}
__device__ __forceinline__ uint32_t pack_h2(float a, float b) {
    __half2 h = __float22half2_rn(make_float2(a, b));
    return *reinterpret_cast<uint32_t*>(&h);
}
__device__ __forceinline__ float ex2f(float x) {
    float r; asm("ex2.approx.ftz.f32 %0, %1;" : "=f"(r) : "f"(x)); return r;
}

// ---------------------------------------------------------------------------
// Fused SMEM layout (per buffer)
// ---------------------------------------------------------------------------
#define SR_B     144u     // R tile [128 n][64 k] fp16
#define SW_B     272u     // W' tile [72 dh][128 n] fp16
#define OFF_RH   0u       // 18432 B
#define OFF_WH   18432u   // 19584 B
#define OFF_CR2  38016u   // float[128]
#define BUF_B    38528u
#define SMEM_BYTES (2u * BUF_B)    // 77056 (zstage [256][68] f32 = 69632 fits)

// out-phase SMEM layout (reuses the same dynamic smem; 73728 <= 77056)
#define OB_STRIDE 144u
#define OB_A      0u
#define OB_BH     18432u
#define OB_BUF    36864u

// ---------------------------------------------------------------------------
// Unified prep kernel. Block ranges:
//   [0, 2048)    : cR2 + fp16 R split   [2048, 2304) : W'   [2304, 2368) : W_O^T
// Block 0 also resets the per-row-group barriers for this graph replay.
// ---------------------------------------------------------------------------
__global__ void __launch_bounds__(256)
prep_all(const float* __restrict__ R, const float* __restrict__ q,
         const float* __restrict__ W, const float* __restrict__ WO)
{
    const int bid = blockIdx.x;
    if (bid == 0 && threadIdx.x < 16) g_barr[threadIdx.x] = 0;

    if (bid < 2048) {
        int wid  = threadIdx.x >> 5, lane = threadIdx.x & 31;
        int idx  = bid * 8 + wid;
        const float* r = R + (size_t)idx * DIM;
        float v0 = r[lane], v1 = r[lane + 32];
        g_RH[(size_t)idx * DIM + lane]      = __float2half_rn(v0);
        g_RH[(size_t)idx * DIM + lane + 32] = __float2half_rn(v1);
        float s = v0 * v0 + v1 * v1;
        #pragma unroll
        for (int m = 16; m >= 1; m >>= 1) s += __shfl_xor_sync(0xffffffffu, s, m);
        if (lane == 0) g_cR2[idx] = C2EXP * s;
    } else if (bid < 2304) {
        __shared__ float sm[64][65];
        __shared__ float sqa[64];
        int b2 = bid - 2048;
        int h  = b2 >> 5;
        int n0 = (b2 & 31) * 64;
        for (int t = threadIdx.x; t < 4096; t += 256) {
            int i = t >> 6, d = t & 63;
            sm[i][d] = W[((size_t)(h * NLAND + n0 + i)) * DIM + d];
        }
        if (threadIdx.x < 64) {
            float qq = q[h * NLAND + n0 + threadIdx.x];
            qq = (qq > 0.f ? qq : 0.f) + EPS_C;
            sqa[threadIdx.x] = rsqrtf(qq);
        }
        __syncthreads();
        for (int t = threadIdx.x; t < 4096; t += 256) {
            int d = t >> 6, i = t & 63;
            float v = sm[i][d] * sqa[i];
            g_WPH[((size_t)h * 72 + d) * NLAND + n0 + i] = __float2half_rn(v);
        }
        for (int t = threadIdx.x; t < 64 * 8; t += 256) {
            int rr = 64 + (t >> 6), i = t & 63;
            float v = (rr == 64) ? 1.0f : (rr == 65 ? sqa[i] : 0.0f);
            g_WPH[((size_t)h * 72 + rr) * NLAND + n0 + i] = __float2half_rn(v);
        }
    } else {
        __shared__ float sm[64][65];
        int b3 = bid - 2304;
        int kb = b3 >> 3, cb = b3 & 7;
        int k0 = kb * 64, c0 = cb * 64;
        for (int t = threadIdx.x; t < 4096; t += 256) {
            int i = t >> 6, d = t & 63;
            sm[i][d] = WO[(size_t)(k0 + i) * DOUT + c0 + d];
        }
        __syncthreads();
        for (int t = threadIdx.x; t < 4096; t += 256) {
            int d = t >> 6, i = t & 63;
            g_WOH[(size_t)(c0 + d) * DOUT + k0 + i] = __float2half_rn(sm[i][d]);
        }
    }
}

// ---------------------------------------------------------------------------
// Fused kernel
// ---------------------------------------------------------------------------
__device__ __forceinline__ void issue_tile_loads(char* smem, int buf, int h, int n0,
                                                 int tid)
{
    uint32_t sb = smem_u32(smem) + (uint32_t)buf * BUF_B;
    const __half* rh = g_RH + ((size_t)h * NLAND + n0) * DIM;
    #pragma unroll
    for (int i = tid; i < 1024; i += 256) {
        int row = i >> 3, u = i & 7;
        cp16(sb + OFF_RH + row * SR_B + u * 16, rh + row * DIM + u * 8);
    }
    const __half* wh = g_WPH + (size_t)h * 72 * NLAND + n0;
    for (int i = tid; i < 1152; i += 256) {
        int row = i >> 4, u = i & 15;
        cp16(sb + OFF_WH + row * SW_B + u * 16, wh + (size_t)row * NLAND + u * 8);
    }
    if (tid < 32)
        cp16(sb + OFF_CR2 + tid * 16, g_cR2 + h * NLAND + n0 + tid * 4);
}

__device__ __forceinline__ void issue_out_loads(char* smem, int buf, int row0,
                                                int col0, int k0, int tid)
{
    uint32_t sb = smem_u32(smem) + (uint32_t)buf * OB_BUF;
    #pragma unroll
    for (int i = tid; i < 1024; i += 256) {
        int row = i >> 3, u = i & 7;
        cp16(sb + OB_A  + row * OB_STRIDE + u * 16,
             g_Y + (size_t)(row0 + row) * DOUT + k0 + u * 8);
        cp16(sb + OB_BH + row * OB_STRIDE + u * 16,
             g_WOH + (size_t)(col0 + row) * DOUT + k0 + u * 8);
    }
}

// GEMM1 for one 16-landmark group: 4 ldm + 16 mma into cb[4][4]
__device__ __forceinline__ void gemm1_group(float cb[4][4], uint32_t rbH, int ntp,
                                            const uint32_t zh[4][8])
{
    #pragma unroll
    for (int a = 0; a < 4; a++)
        #pragma unroll
        for (int e = 0; e < 4; e++) cb[a][e] = 0.f;
    #pragma unroll
    for (int kc = 0; kc < 4; kc++) {
        uint32_t rh[4];
        ldm_x4(rh, rbH + (uint32_t)(ntp * 16) * SR_B + (uint32_t)kc * 32);
        mma_f16(cb[0], &zh[kc][0], rh[0], rh[1]);
        mma_f16(cb[1], &zh[kc][0], rh[2], rh[3]);
        mma_f16(cb[2], &zh[kc][4], rh[0], rh[1]);
        mma_f16(cb[3], &zh[kc][4], rh[2], rh[3]);
    }
}

__global__ void __launch_bounds__(256, 1)
fused_mma(const float* __restrict__ z, const float* __restrict__ bO,
          float* __restrict__ out)
{
    extern __shared__ __align__(16) char smem[];
    const int tid  = threadIdx.x;
    const int warp = tid >> 5;
    const int lane = tid & 31;
    const int h    = blockIdx.y;
    const int row0 = blockIdx.x * BM;
    const int g    = lane >> 2;
    const int t4   = lane & 3;
    const int wrow = warp * 32;
    const uint32_t sbase = smem_u32(smem);

    const int n_add = ((lane >> 4) & 1) * 8 + (lane & 7);
    const int k_add = ((lane >> 3) & 1) * 8;
    const uint32_t laneR = (uint32_t)(n_add * SR_B + k_add * 2);
    const uint32_t laneW = (uint32_t)(n_add * SW_B + k_add * 2);

    // ---- stage z fp32 into smem FIRST (uses both tile buffers transiently) ----
    float* zstage = (float*)smem;               // [256][68] = 69632 B
    {
        const float4* zsrc = reinterpret_cast<const float4*>(z);
        #pragma unroll
        for (int i = tid; i < BM * 16; i += 256) {
            int r = i >> 4, c4 = i & 15;
            float4 v = zsrc[(((size_t)(row0 + r) * NHEAD + h) * DIM >> 2) + c4];
            *reinterpret_cast<float4*>(zstage + r * 68 + c4 * 4) = v;
        }
    }
    __syncthreads();

    // this thread's 4 rows (two 16-row A groups)
    const int ra0 = wrow + g, ra1 = ra0 + 8;
    const int rb0 = wrow + 16 + g, rb1 = rb0 + 8;

    float z2[4] = {0.f, 0.f, 0.f, 0.f};
    #pragma unroll
    for (int k = 0; k < DIM; k++) {
        float v0 = zstage[ra0 * 68 + k];
        float v1 = zstage[ra1 * 68 + k];
        float v2 = zstage[rb0 * 68 + k];
        float v3 = zstage[rb1 * 68 + k];
        z2[0] += v0 * v0; z2[1] += v1 * v1;
        z2[2] += v2 * v2; z2[3] += v3 * v3;
    }
    float esc[4];
    #pragma unroll
    for (int e = 0; e < 4; e++) esc[e] = ex2f(C2EXP * z2[e]);

    uint32_t zh[4][8];
    #pragma unroll
    for (int kc = 0; kc < 4; kc++) {
        int k0 = kc * 16 + 2 * t4;
        zh[kc][0] = pack_h2(zstage[ra0 * 68 + k0],     zstage[ra0 * 68 + k0 + 1]);
        zh[kc][1] = pack_h2(zstage[ra1 * 68 + k0],     zstage[ra1 * 68 + k0 + 1]);
        zh[kc][2] = pack_h2(zstage[ra0 * 68 + k0 + 8], zstage[ra0 * 68 + k0 + 9]);
        zh[kc][3] = pack_h2(zstage[ra1 * 68 + k0 + 8], zstage[ra1 * 68 + k0 + 9]);
        zh[kc][4] = pack_h2(zstage[rb0 * 68 + k0],     zstage[rb0 * 68 + k0 + 1]);
        zh[kc][5] = pack_h2(zstage[rb1 * 68 + k0],     zstage[rb1 * 68 + k0 + 1]);
        zh[kc][6] = pack_h2(zstage[rb0 * 68 + k0 + 8], zstage[rb0 * 68 + k0 + 9]);
        zh[kc][7] = pack_h2(zstage[rb1 * 68 + k0 + 8], zstage[rb1 * 68 + k0 + 9]);
    }
    __syncthreads();   // zstage region free -> start cp.async pipeline

    issue_tile_loads(smem, 0, h, 0, tid);
    CP_COMMIT();

    float y[16][4];    // y: [0..7] group A rows, [8..15] group B rows
    float yp0[4], yp1[4];
    #pragma unroll
    for (int nt = 0; nt < 16; nt++)
        #pragma unroll
        for (int e = 0; e < 4; e++) y[nt][e] = 0.f;
    #pragma unroll
    for (int e = 0; e < 4; e++) { yp0[e] = 0.f; yp1[e] = 0.f; }

    for (int t = 0; t < 16; t++) {
        const int cur = t & 1;
        if (t < 15) {
            issue_tile_loads(smem, cur ^ 1, h, (t + 1) * 128, tid);
            CP_COMMIT();
            CP_WAIT1();
        } else {
            CP_WAIT0();
        }
        __syncthreads();

        const uint32_t sb  = sbase + (uint32_t)cur * BUF_B;
        const uint32_t rbH = sb + OFF_RH + laneR;
        const uint32_t wbH = sb + OFF_WH + laneW;
        const float* crp = (const float*)(smem + cur * BUF_B + OFF_CR2);

        // ---- software-pipelined: GEMM1(ntp+1) issues before epilogue(ntp) ----
        float cb[2][4][4];
        gemm1_group(cb[0], rbH, 0, zh);

        #pragma unroll
        for (int ntp = 0; ntp < 8; ntp++) {
            const int pc = ntp & 1, pn = pc ^ 1;
            if (ntp < 7) gemm1_group(cb[pn], rbH, ntp + 1, zh);

            const int col0 = (2 * ntp) * 8 + 2 * t4;
            const int col1 = col0 + 8;
            float cr0 = crp[col0], cr1 = crp[col0 + 1];
            float cr2 = crp[col1], cr3 = crp[col1 + 1];

            uint32_t a0[4], a1[4];
            a0[0] = pack_h2(ex2f(fminf(fmaf(cb[pc][0][0], LOG2E, cr0), 15.f)),
                            ex2f(fminf(fmaf(cb[pc][0][1], LOG2E, cr1), 15.f)));
            a0[1] = pack_h2(ex2f(fminf(fmaf(cb[pc][0][2], LOG2E, cr0), 15.f)),
                            ex2f(fminf(fmaf(cb[pc][0][3], LOG2E, cr1), 15.f)));
            a0[2] = pack_h2(ex2f(fminf(fmaf(cb[pc][1][0], LOG2E, cr2), 15.f)),
                            ex2f(fminf(fmaf(cb[pc][1][1], LOG2E, cr3), 15.f)));
            a0[3] = pack_h2(ex2f(fminf(fmaf(cb[pc][1][2], LOG2E, cr2), 15.f)),
                            ex2f(fminf(fmaf(cb[pc][1][3], LOG2E, cr3), 15.f)));
            a1[0] = pack_h2(ex2f(fminf(fmaf(cb[pc][2][0], LOG2E, cr0), 15.f)),
                            ex2f(fminf(fmaf(cb[pc][2][1], LOG2E, cr1), 15.f)));
            a1[1] = pack_h2(ex2f(fminf(fmaf(cb[pc][2][2], LOG2E, cr0), 15.f)),
                            ex2f(fminf(fmaf(cb[pc][2][3], LOG2E, cr1), 15.f)));
            a1[2] = pack_h2(ex2f(fminf(fmaf(cb[pc][3][0], LOG2E, cr2), 15.f)),
                            ex2f(fminf(fmaf(cb[pc][3][1], LOG2E, cr3), 15.f)));
            a1[3] = pack_h2(ex2f(fminf(fmaf(cb[pc][3][2], LOG2E, cr2), 15.f)),
                            ex2f(fminf(fmaf(cb[pc][3][3], LOG2E, cr3), 15.f)));

            uint32_t kcOff = (uint32_t)ntp * 32;
            uint32_t w0[4], w1[4], w2[4], w3[4], wp[2];
            ldm_x4(w0, wbH + kcOff);
            ldm_x4(w1, wbH + 16 * SW_B + kcOff);
            ldm_x4(w2, wbH + 32 * SW_B + kcOff);
            ldm_x4(w3, wbH + 48 * SW_B + kcOff);
            ldm_x2(wp, wbH + 64 * SW_B + kcOff);
            // group A
            mma_f16(y[0], a0, w0[0], w0[1]);
            mma_f16(y[1], a0, w0[2], w0[3]);
            mma_f16(y[2], a0, w1[0], w1[1]);
            mma_f16(y[3], a0, w1[2], w1[3]);
            mma_f16(y[4], a0, w2[0], w2[1]);
            mma_f16(y[5], a0, w2[2], w2[3]);
            mma_f16(y[6], a0, w3[0], w3[1]);
            mma_f16(y[7], a0, w3[2], w3[3]);
            mma_f16(yp0,  a0, wp[0], wp[1]);
            // group B
            mma_f16(y[8],  a1, w0[0], w0[1]);
            mma_f16(y[9],  a1, w0[2], w0[3]);
            mma_f16(y[10], a1, w1[0], w1[1]);
            mma_f16(y[11], a1, w1[2], w1[3]);
            mma_f16(y[12], a1, w2[0], w2[1]);
            mma_f16(y[13], a1, w2[2], w2[3]);
            mma_f16(y[14], a1, w3[0], w3[1]);
            mma_f16(y[15], a1, w3[2], w3[3]);
            mma_f16(yp1,  a1, wp[0], wp[1]);
        }
        __syncthreads();
    }

    // ---- p1'/p2' live in yp of t4==0 lanes (cols 64,65); broadcast ----
    int src = lane & 28;
    float P1[4], P2[4];
    P1[0] = __shfl_sync(0xffffffffu, yp0[0], src);
    P2[0] = __shfl_sync(0xffffffffu, yp0[1], src);
    P1[1] = __shfl_sync(0xffffffffu, yp0[2], src);
    P2[1] = __shfl_sync(0xffffffffu, yp0[3], src);
    P1[2] = __shfl_sync(0xffffffffu, yp1[0], src);
    P2[2] = __shfl_sync(0xffffffffu, yp1[1], src);
    P1[3] = __shfl_sync(0xffffffffu, yp1[2], src);
    P2[3] = __shfl_sync(0xffffffffu, yp1[3], src);

    float f[4];
    #pragma unroll
    for (int e = 0; e < 4; e++) {
        float p1 = esc[e] * P1[e], p2 = esc[e] * P2[e];
        float cc = rsqrtf(fmaxf(p1, EPS_C));
        f[e] = cc / fmaxf(cc * p2, EPS_C) * esc[e];
    }

    // ---- write y as single fp16 (4 rows) ----
    const int rows[4] = {ra0, ra1, rb0, rb1};
    #pragma unroll
    for (int e = 0; e < 4; e++) {
        size_t o = (size_t)(row0 + rows[e]) * DOUT + h * DIM + 2 * t4;
        int base = (e >> 1) * 8;
        int lohi = e & 1;
        #pragma unroll
        for (int nt = 0; nt < 8; nt++) {
            *reinterpret_cast<uint32_t*>(g_Y + o + nt * 8) =
                pack_h2(y[base + nt][2 * lohi] * f[e],
                        y[base + nt][2 * lohi + 1] * f[e]);
        }
    }

    // =======================================================================
    // Per-row-group barrier: out-tile rows [bx*256, bx*256+256) need only the
    // 8 phase-1 CTAs with the same blockIdx.x (all heads).
    // g_barr[] reset by prep_all earlier in this graph replay.
    // =======================================================================
    __threadfence();
    __syncthreads();
    if (tid == 0) {
        atomicAdd(&g_barr[blockIdx.x], 1);
        while (atomicAdd(&g_barr[blockIdx.x], 0) < NHEAD) __nanosleep(32);
    }
    __syncthreads();

    // =======================================================================
    // Phase 2: out = y @ W_O + b_O. Grid (16,8) -> (row32, col4) tiles.
    // id>>3 == blockIdx.x, so the wait above covers exactly our row range.
    // =======================================================================
    const int id    = blockIdx.x * 8 + blockIdx.y;   // 0..127
    const int row0o = (id >> 2) * 128;
    const int col0o = (id & 3) * 128;
    const int wrow2 = warp * 16;
    const uint32_t laneO = (uint32_t)(n_add * OB_STRIDE + k_add * 2);

    issue_out_loads(smem, 0, row0o, col0o, 0, tid);
    CP_COMMIT();

    float yo[16][4];
    #pragma unroll
    for (int nt = 0; nt < 16; nt++)
        #pragma unroll
        for (int e = 0; e < 4; e++) yo[nt][e] = 0.f;

    for (int kb = 0; kb < 8; kb++) {
        const int cur = kb & 1;
        if (kb < 7) {
            issue_out_loads(smem, cur ^ 1, row0o, col0o, (kb + 1) * 64, tid);
            CP_COMMIT();
            CP_WAIT1();
        } else {
            CP_WAIT0();
        }
        __syncthreads();

        const uint32_t sb = sbase + (uint32_t)cur * OB_BUF;
        const uint32_t aA = sb + OB_A  + (uint32_t)wrow2 * OB_STRIDE + laneO;
        const uint32_t bH = sb + OB_BH + laneO;

        #pragma unroll
        for (int kc = 0; kc < 4; kc++) {
            uint32_t ta[4];
            ldm_x4(ta, aA + kc * 32);
            uint32_t a[4] = {ta[0], ta[2], ta[1], ta[3]};   // validated permute

            #pragma unroll
            for (int np = 0; np < 4; np++) {
                uint32_t oA = (uint32_t)((2 * np) * 16) * OB_STRIDE + (uint32_t)kc * 32;
                uint32_t oB = (uint32_t)((2 * np + 1) * 16) * OB_STRIDE + (uint32_t)kc * 32;
                uint32_t whA[4], whB[4];
                ldm_x4(whA, bH + oA);
                ldm_x4(whB, bH + oB);
                mma_f16(yo[4 * np + 0], a, whA[0], whA[1]);
                mma_f16(yo[4 * np + 1], a, whA[2], whA[3]);
                mma_f16(yo[4 * np + 2], a, whB[0], whB[1]);
                mma_f16(yo[4 * np + 3], a, whB[2], whB[3]);
            }
        }
        __syncthreads();
    }

    const int r0o = row0o + wrow2 + g, r1o = r0o + 8;
    #pragma unroll
    for (int nt = 0; nt < 16; nt++) {
        int col = col0o + nt * 8 + 2 * t4;
        float b0 = bO[col], b1 = bO[col + 1];
        *reinterpret_cast<float2*>(out + (size_t)r0o * DOUT + col) =
            make_float2(yo[nt][0] + b0, yo[nt][1] + b1);
        *reinterpret_cast<float2*>(out + (size_t)r1o * DOUT + col) =
            make_float2(yo[nt][2] + b0, yo[nt][3] + b1);
    }
}

// ---------------------------------------------------------------------------
extern "C" void kernel_launch(void* const* d_in, const int* in_sizes, int n_in,
                              void* d_out, int out_size)
{
    const float* z  = (const float*)d_in[0];   // (4,1024,8,64)
    const float* R  = (const float*)d_in[1];   // (8,2048,64)
    const float* q  = (const float*)d_in[2];   // (8,2048)
    const float* W  = (const float*)d_in[3];   // (8,2048,64)
    const float* WO = (const float*)d_in[4];   // (512,512)
    const float* bO = (const float*)d_in[5];   // (512)
    float* out = (float*)d_out;                // (4,1024,512)
    (void)in_sizes; (void)n_in; (void)out_size;

    cudaFuncSetAttribute(fused_mma, cudaFuncAttributeMaxDynamicSharedMemorySize,
                         SMEM_BYTES);

    prep_all<<<2368, 256>>>(R, q, W, WO);      // also resets g_barr[]

    dim3 gridF(BS_ROWS / BM, NHEAD);           // (16, 8) = 128 CTAs, one wave
    fused_mma<<<gridF, 256, SMEM_BYTES>>>(z, bO, out);
}